// round 2
// baseline (speedup 1.0000x reference)
#include <cuda_runtime.h>
#include <cuda_bf16.h>

// Problem constants
#define BATCH 8
#define CH    512
#define NPIX  4096   // 64*64

// ---------------- scratch (device globals: allocation-free) ----------------
__device__ float g_G[BATCH * CH * CH];    // X X^T per batch
__device__ float g_S[BATCH * CH * CH];    // logits -> attn
__device__ float g_T[BATCH * CH * CH];    // Wq*G, then A*Wv
__device__ float g_s[BATCH * CH];         // row sums of X
__device__ float g_qs[BATCH * CH];        // Wq * s
__device__ float g_ks2[BATCH * CH];       // Wk * s + N*bk
__device__ float g_Abv[BATCH * CH];       // A * bv

// ---------------- reductions ----------------
__device__ __forceinline__ float blockReduceSum(float v, volatile float* red, int t, int nwarp) {
    #pragma unroll
    for (int o = 16; o > 0; o >>= 1) v += __shfl_xor_sync(0xffffffffu, v, o);
    if ((t & 31) == 0) red[t >> 5] = v;
    __syncthreads();
    float r = red[0];
    if (t == 0) { for (int i = 1; i < nwarp; i++) r += red[i]; red[0] = r; }
    __syncthreads();
    r = red[0];
    __syncthreads();
    return r;
}

__device__ __forceinline__ float blockReduceMax(float v, volatile float* red, int t, int nwarp) {
    #pragma unroll
    for (int o = 16; o > 0; o >>= 1) v = fmaxf(v, __shfl_xor_sync(0xffffffffu, v, o));
    if ((t & 31) == 0) red[t >> 5] = v;
    __syncthreads();
    float r = red[0];
    if (t == 0) { for (int i = 1; i < nwarp; i++) r = fmaxf(r, red[i]); red[0] = r; }
    __syncthreads();
    r = red[0];
    __syncthreads();
    return r;
}

// ---------------- rowsum: s[b][c] = sum_n x[b][c][n] ----------------
__global__ void rowsum_kernel(const float* __restrict__ x, float* __restrict__ s) {
    __shared__ float red[8];
    int row = blockIdx.x;                       // b*CH + c  (4096 rows)
    const float4* p4 = (const float4*)(x + (long)row * NPIX);
    int t = threadIdx.x;                        // 256 threads
    float a = 0.f;
    #pragma unroll
    for (int n = t; n < NPIX / 4; n += 256) {
        float4 v = p4[n];
        a += (v.x + v.y) + (v.z + v.w);
    }
    float tot = blockReduceSum(a, red, t, 8);
    if (t == 0) s[row] = tot;
}

// ---------------- matvec2: qs = Wq s ; ks2 = Wk s + N*bk ----------------
__global__ void matvec2_kernel(const float* __restrict__ wq, const float* __restrict__ wk,
                               const float* __restrict__ bk,
                               const float* __restrict__ s,
                               float* __restrict__ qs, float* __restrict__ ks2) {
    __shared__ float red[4];
    int bi = blockIdx.x;                        // b*CH + i
    int b = bi >> 9, i = bi & (CH - 1);
    const float* sv = s + (long)b * CH;
    int t = threadIdx.x;                        // 128 threads
    float aq = 0.f, ak = 0.f;
    for (int c = t; c < CH; c += 128) {
        float sc = sv[c];
        aq = fmaf(wq[i * CH + c], sc, aq);
        ak = fmaf(wk[i * CH + c], sc, ak);
    }
    #pragma unroll
    for (int o = 16; o > 0; o >>= 1) {
        aq += __shfl_xor_sync(0xffffffffu, aq, o);
        ak += __shfl_xor_sync(0xffffffffu, ak, o);
    }
    if ((t & 31) == 0) red[t >> 5] = aq;
    __syncthreads();
    float tq = red[0];
    if (t == 0) { for (int w = 1; w < 4; w++) tq += red[w]; }
    __syncthreads();
    if ((t & 31) == 0) red[t >> 5] = ak;
    __syncthreads();
    if (t == 0) {
        float tk = red[0];
        for (int w = 1; w < 4; w++) tk += red[w];
        qs[bi] = tq;
        ks2[bi] = tk + (float)NPIX * bk[i];
    }
}

// ---------------- tiled SGEMM, NN: C = A(MxK) * B(KxN), row-major ----------------
// BM=BN=128, BK=16, 256 threads, 8x8 per thread. All dims multiples of 128/16.
#define BM 128
#define BN 128
#define BKK 16

__global__ __launch_bounds__(256, 2)
void gemm_nn_kernel(const float* __restrict__ A, long strideA,
                    const float* __restrict__ Bm, long strideB,
                    float* __restrict__ Cm, long strideC,
                    int K, int lda, int ldb, int ldc,
                    const float* __restrict__ rowBias, long strideRB) {
    __shared__ float As[BKK][BM + 4];
    __shared__ float Bs[BKK][BN + 4];
    int b = blockIdx.z;
    A += (long)b * strideA;
    Bm += (long)b * strideB;
    Cm += (long)b * strideC;
    int i0 = blockIdx.y * BM;
    int j0 = blockIdx.x * BN;
    int t = threadIdx.x;
    int tx = t & 15, ty = t >> 4;
    float acc[8][8] = {};
    for (int k0 = 0; k0 < K; k0 += BKK) {
        #pragma unroll
        for (int u = 0; u < 2; u++) {
            int idx = t + u * 256;
            int ar = idx >> 2, akc = (idx & 3) * 4;
            float4 av = *(const float4*)(A + (long)(i0 + ar) * lda + k0 + akc);
            As[akc + 0][ar] = av.x; As[akc + 1][ar] = av.y;
            As[akc + 2][ar] = av.z; As[akc + 3][ar] = av.w;
            int br = idx >> 5, bc = (idx & 31) * 4;
            *(float4*)(&Bs[br][bc]) = *(const float4*)(Bm + (long)(k0 + br) * ldb + j0 + bc);
        }
        __syncthreads();
        #pragma unroll
        for (int kk = 0; kk < BKK; kk++) {
            float a[8], bb[8];
            *(float4*)(a)      = *(const float4*)(&As[kk][ty * 4]);
            *(float4*)(a + 4)  = *(const float4*)(&As[kk][64 + ty * 4]);
            *(float4*)(bb)     = *(const float4*)(&Bs[kk][tx * 4]);
            *(float4*)(bb + 4) = *(const float4*)(&Bs[kk][64 + tx * 4]);
            #pragma unroll
            for (int i = 0; i < 8; i++)
                #pragma unroll
                for (int j = 0; j < 8; j++)
                    acc[i][j] = fmaf(a[i], bb[j], acc[i][j]);
        }
        __syncthreads();
    }
    const float* rb = rowBias ? rowBias + (long)b * strideRB : nullptr;
    #pragma unroll
    for (int ii = 0; ii < 8; ii++) {
        int row = i0 + ((ii < 4) ? (ty * 4 + ii) : (64 + ty * 4 + ii - 4));
        float bias = rb ? rb[row] : 0.f;
        float4 o0, o1;
        o0.x = acc[ii][0] + bias; o0.y = acc[ii][1] + bias;
        o0.z = acc[ii][2] + bias; o0.w = acc[ii][3] + bias;
        o1.x = acc[ii][4] + bias; o1.y = acc[ii][5] + bias;
        o1.z = acc[ii][6] + bias; o1.w = acc[ii][7] + bias;
        *(float4*)(Cm + (long)row * ldc + j0 + tx * 4)      = o0;
        *(float4*)(Cm + (long)row * ldc + j0 + 64 + tx * 4) = o1;
    }
}

// ---------------- tiled SGEMM, NT: C = A(MxK) * B(NxK)^T, row-major ----------------
// Optional rank-1 epilogue: C[i][j] += u1[i]*v1[j] + u2[i]*v2[j]
__global__ __launch_bounds__(256, 2)
void gemm_nt_kernel(const float* __restrict__ A, long strideA,
                    const float* __restrict__ Bm, long strideB,
                    float* __restrict__ Cm, long strideC,
                    int K, int lda, int ldb, int ldc,
                    const float* __restrict__ u1, long su1,
                    const float* __restrict__ v1, long sv1,
                    const float* __restrict__ u2, long su2,
                    const float* __restrict__ v2, long sv2) {
    __shared__ float As[BKK][BM + 4];
    __shared__ float Bs[BKK][BN + 4];
    int b = blockIdx.z;
    A += (long)b * strideA;
    Bm += (long)b * strideB;
    Cm += (long)b * strideC;
    int i0 = blockIdx.y * BM;
    int j0 = blockIdx.x * BN;
    int t = threadIdx.x;
    int tx = t & 15, ty = t >> 4;
    float acc[8][8] = {};
    for (int k0 = 0; k0 < K; k0 += BKK) {
        #pragma unroll
        for (int u = 0; u < 2; u++) {
            int idx = t + u * 256;
            int ar = idx >> 2, akc = (idx & 3) * 4;
            float4 av = *(const float4*)(A + (long)(i0 + ar) * lda + k0 + akc);
            As[akc + 0][ar] = av.x; As[akc + 1][ar] = av.y;
            As[akc + 2][ar] = av.z; As[akc + 3][ar] = av.w;
            float4 bw = *(const float4*)(Bm + (long)(j0 + ar) * ldb + k0 + akc);
            Bs[akc + 0][ar] = bw.x; Bs[akc + 1][ar] = bw.y;
            Bs[akc + 2][ar] = bw.z; Bs[akc + 3][ar] = bw.w;
        }
        __syncthreads();
        #pragma unroll
        for (int kk = 0; kk < BKK; kk++) {
            float a[8], bb[8];
            *(float4*)(a)      = *(const float4*)(&As[kk][ty * 4]);
            *(float4*)(a + 4)  = *(const float4*)(&As[kk][64 + ty * 4]);
            *(float4*)(bb)     = *(const float4*)(&Bs[kk][tx * 4]);
            *(float4*)(bb + 4) = *(const float4*)(&Bs[kk][64 + tx * 4]);
            #pragma unroll
            for (int i = 0; i < 8; i++)
                #pragma unroll
                for (int j = 0; j < 8; j++)
                    acc[i][j] = fmaf(a[i], bb[j], acc[i][j]);
        }
        __syncthreads();
    }
    bool hasR1 = (u1 != nullptr);
    float u1r[8], u2r[8], v1c[8], v2c[8];
    if (hasR1) {
        const float* pu1 = u1 + (long)b * su1;
        const float* pv1 = v1 + (long)b * sv1;
        const float* pu2 = u2 + (long)b * su2;
        const float* pv2 = v2 + (long)b * sv2;
        #pragma unroll
        for (int ii = 0; ii < 8; ii++) {
            int row = i0 + ((ii < 4) ? (ty * 4 + ii) : (64 + ty * 4 + ii - 4));
            u1r[ii] = pu1[row]; u2r[ii] = pu2[row];
        }
        #pragma unroll
        for (int jj = 0; jj < 8; jj++) {
            int col = j0 + ((jj < 4) ? (tx * 4 + jj) : (64 + tx * 4 + jj - 4));
            v1c[jj] = pv1[col]; v2c[jj] = pv2[col];
        }
    }
    #pragma unroll
    for (int ii = 0; ii < 8; ii++) {
        int row = i0 + ((ii < 4) ? (ty * 4 + ii) : (64 + ty * 4 + ii - 4));
        float vals[8];
        #pragma unroll
        for (int jj = 0; jj < 8; jj++) {
            float v = acc[ii][jj];
            if (hasR1) v += u1r[ii] * v1c[jj] + u2r[ii] * v2c[jj];
            vals[jj] = v;
        }
        *(float4*)(Cm + (long)row * ldc + j0 + tx * 4)      = *(float4*)(vals);
        *(float4*)(Cm + (long)row * ldc + j0 + 64 + tx * 4) = *(float4*)(vals + 4);
    }
}

// ---------------- softmax rows of S (in place) + Abv = A*bv ----------------
__global__ void softmax_abv_kernel(float* __restrict__ S, const float* __restrict__ bv,
                                   float* __restrict__ Abv) {
    __shared__ float red[8];
    int row = blockIdx.x;                       // b*CH + i (4096 rows)
    float* p = S + (long)row * CH;
    int t = threadIdx.x;                        // 256 threads, 2 elems each
    float v0 = p[t], v1 = p[t + 256];
    float m = blockReduceMax(fmaxf(v0, v1), red, t, 8);
    float e0 = __expf(v0 - m), e1 = __expf(v1 - m);
    float tot = blockReduceSum(e0 + e1, red, t, 8);
    float inv = 1.0f / tot;
    float a0 = e0 * inv, a1 = e1 * inv;
    p[t] = a0; p[t + 256] = a1;
    float d = blockReduceSum(a0 * bv[t] + a1 * bv[t + 256], red, t, 8);
    if (t == 0) Abv[row] = d;
}

// ---------------- launch ----------------
extern "C" void kernel_launch(void* const* d_in, const int* in_sizes, int n_in,
                              void* d_out, int out_size) {
    const float* x  = (const float*)d_in[0];
    const float* wq = (const float*)d_in[1];
    const float* bq = (const float*)d_in[2];
    const float* wk = (const float*)d_in[3];
    const float* bk = (const float*)d_in[4];
    const float* wv = (const float*)d_in[5];
    const float* bv = (const float*)d_in[6];
    float* out = (float*)d_out;

    float *G, *S, *T, *s, *qs, *ks2, *Abv;
    cudaGetSymbolAddress((void**)&G,   g_G);
    cudaGetSymbolAddress((void**)&S,   g_S);
    cudaGetSymbolAddress((void**)&T,   g_T);
    cudaGetSymbolAddress((void**)&s,   g_s);
    cudaGetSymbolAddress((void**)&qs,  g_qs);
    cudaGetSymbolAddress((void**)&ks2, g_ks2);
    cudaGetSymbolAddress((void**)&Abv, g_Abv);

    const long CN = (long)CH * NPIX;   // per-batch x stride
    const long CC = (long)CH * CH;

    // 1) row sums of X
    rowsum_kernel<<<BATCH * CH, 256>>>(x, s);

    // 2) G[b] = X[b] * X[b]^T   (NT, K=4096)
    gemm_nt_kernel<<<dim3(CH / BN, CH / BM, BATCH), 256>>>(
        x, CN, x, CN, G, CC, NPIX, NPIX, NPIX, CH,
        nullptr, 0, nullptr, 0, nullptr, 0, nullptr, 0);

    // 3) qs = Wq s ; ks2 = Wk s + N*bk
    matvec2_kernel<<<BATCH * CH, 128>>>(wq, wk, bk, s, qs, ks2);

    // 4) T[b] = Wq * G[b]   (NN, K=512)
    gemm_nn_kernel<<<dim3(CH / BN, CH / BM, BATCH), 256>>>(
        wq, 0, G, CC, T, CC, CH, CH, CH, CH, nullptr, 0);

    // 5) S[b] = T[b] * Wk^T + qs[i]*bk[j] + bq[i]*ks2[j]   (NT, K=512)
    gemm_nt_kernel<<<dim3(CH / BN, CH / BM, BATCH), 256>>>(
        T, CC, wk, 0, S, CC, CH, CH, CH, CH,
        qs, CH, bk, 0, bq, 0, ks2, CH);

    // 6) softmax rows -> A (in place), Abv = A*bv
    softmax_abv_kernel<<<BATCH * CH, 256>>>(S, bv, Abv);

    // 7) M[b] = A[b] * Wv   (NN, K=512) -> reuse T
    gemm_nn_kernel<<<dim3(CH / BN, CH / BM, BATCH), 256>>>(
        S, CC, wv, 0, T, CC, CH, CH, CH, CH, nullptr, 0);

    // 8) out[b] = M[b] * X[b] + Abv[i]   (NN, K=512, N=4096)
    gemm_nn_kernel<<<dim3(NPIX / BN, CH / BM, BATCH), 256>>>(
        T, CC, x, CN, out, CN, CH, CH, NPIX, NPIX, Abv, CH);
}

// round 3
// speedup vs baseline: 1.0019x; 1.0019x over previous
#include <cuda_runtime.h>
#include <cuda_bf16.h>

// Problem constants
#define BATCH 8
#define CH    512
#define NPIX  4096   // 64*64

// ---------------- scratch (device globals: allocation-free) ----------------
__device__ float g_G[BATCH * CH * CH];    // X X^T per batch
__device__ float g_S[BATCH * CH * CH];    // logits -> attn
__device__ float g_T[BATCH * CH * CH];    // Wq*G, then A*Wv
__device__ float g_s[BATCH * CH];         // row sums of X
__device__ float g_qs[BATCH * CH];        // Wq * s
__device__ float g_ks2[BATCH * CH];       // Wk * s + N*bk
__device__ float g_Abv[BATCH * CH];       // A * bv

// ---------------- reductions ----------------
__device__ __forceinline__ float blockReduceSum(float v, volatile float* red, int t, int nwarp) {
    #pragma unroll
    for (int o = 16; o > 0; o >>= 1) v += __shfl_xor_sync(0xffffffffu, v, o);
    if ((t & 31) == 0) red[t >> 5] = v;
    __syncthreads();
    float r = red[0];
    if (t == 0) { for (int i = 1; i < nwarp; i++) r += red[i]; red[0] = r; }
    __syncthreads();
    r = red[0];
    __syncthreads();
    return r;
}

__device__ __forceinline__ float blockReduceMax(float v, volatile float* red, int t, int nwarp) {
    #pragma unroll
    for (int o = 16; o > 0; o >>= 1) v = fmaxf(v, __shfl_xor_sync(0xffffffffu, v, o));
    if ((t & 31) == 0) red[t >> 5] = v;
    __syncthreads();
    float r = red[0];
    if (t == 0) { for (int i = 1; i < nwarp; i++) r = fmaxf(r, red[i]); red[0] = r; }
    __syncthreads();
    r = red[0];
    __syncthreads();
    return r;
}

// ---------------- rowsum: s[b][c] = sum_n x[b][c][n] ----------------
__global__ void rowsum_kernel(const float* __restrict__ x, float* __restrict__ s) {
    __shared__ float red[8];
    int row = blockIdx.x;                       // b*CH + c  (4096 rows)
    const float4* p4 = (const float4*)(x + (long)row * NPIX);
    int t = threadIdx.x;                        // 256 threads
    float a = 0.f;
    #pragma unroll
    for (int n = t; n < NPIX / 4; n += 256) {
        float4 v = p4[n];
        a += (v.x + v.y) + (v.z + v.w);
    }
    float tot = blockReduceSum(a, red, t, 8);
    if (t == 0) s[row] = tot;
}

// ---------------- matvec2: qs = Wq s ; ks2 = Wk s + N*bk ----------------
__global__ void matvec2_kernel(const float* __restrict__ wq, const float* __restrict__ wk,
                               const float* __restrict__ bk,
                               const float* __restrict__ s,
                               float* __restrict__ qs, float* __restrict__ ks2) {
    __shared__ float red[4];
    int bi = blockIdx.x;                        // b*CH + i
    int b = bi >> 9, i = bi & (CH - 1);
    const float* sv = s + (long)b * CH;
    int t = threadIdx.x;                        // 128 threads
    float aq = 0.f, ak = 0.f;
    for (int c = t; c < CH; c += 128) {
        float sc = sv[c];
        aq = fmaf(wq[i * CH + c], sc, aq);
        ak = fmaf(wk[i * CH + c], sc, ak);
    }
    #pragma unroll
    for (int o = 16; o > 0; o >>= 1) {
        aq += __shfl_xor_sync(0xffffffffu, aq, o);
        ak += __shfl_xor_sync(0xffffffffu, ak, o);
    }
    if ((t & 31) == 0) red[t >> 5] = aq;
    __syncthreads();
    float tq = red[0];
    if (t == 0) { for (int w = 1; w < 4; w++) tq += red[w]; }
    __syncthreads();
    if ((t & 31) == 0) red[t >> 5] = ak;
    __syncthreads();
    if (t == 0) {
        float tk = red[0];
        for (int w = 1; w < 4; w++) tk += red[w];
        qs[bi] = tq;
        ks2[bi] = tk + (float)NPIX * bk[i];
    }
}

// ---------------- tiled SGEMM, NN: C = A(MxK) * B(KxN), row-major ----------------
// BM=BN=128, BK=16, 256 threads, 8x8 per thread. All dims multiples of 128/16.
#define BM 128
#define BN 128
#define BKK 16

__global__ __launch_bounds__(256, 2)
void gemm_nn_kernel(const float* __restrict__ A, long strideA,
                    const float* __restrict__ Bm, long strideB,
                    float* __restrict__ Cm, long strideC,
                    int K, int lda, int ldb, int ldc,
                    const float* __restrict__ rowBias, long strideRB) {
    __shared__ float As[BKK][BM + 4];
    __shared__ float Bs[BKK][BN + 4];
    int b = blockIdx.z;
    A += (long)b * strideA;
    Bm += (long)b * strideB;
    Cm += (long)b * strideC;
    int i0 = blockIdx.y * BM;
    int j0 = blockIdx.x * BN;
    int t = threadIdx.x;
    int tx = t & 15, ty = t >> 4;
    float acc[8][8] = {};
    for (int k0 = 0; k0 < K; k0 += BKK) {
        #pragma unroll
        for (int u = 0; u < 2; u++) {
            int idx = t + u * 256;
            int ar = idx >> 2, akc = (idx & 3) * 4;
            float4 av = *(const float4*)(A + (long)(i0 + ar) * lda + k0 + akc);
            As[akc + 0][ar] = av.x; As[akc + 1][ar] = av.y;
            As[akc + 2][ar] = av.z; As[akc + 3][ar] = av.w;
            int br = idx >> 5, bc = (idx & 31) * 4;
            *(float4*)(&Bs[br][bc]) = *(const float4*)(Bm + (long)(k0 + br) * ldb + j0 + bc);
        }
        __syncthreads();
        #pragma unroll
        for (int kk = 0; kk < BKK; kk++) {
            float a[8], bb[8];
            *(float4*)(a)      = *(const float4*)(&As[kk][ty * 4]);
            *(float4*)(a + 4)  = *(const float4*)(&As[kk][64 + ty * 4]);
            *(float4*)(bb)     = *(const float4*)(&Bs[kk][tx * 4]);
            *(float4*)(bb + 4) = *(const float4*)(&Bs[kk][64 + tx * 4]);
            #pragma unroll
            for (int i = 0; i < 8; i++)
                #pragma unroll
                for (int j = 0; j < 8; j++)
                    acc[i][j] = fmaf(a[i], bb[j], acc[i][j]);
        }
        __syncthreads();
    }
    const float* rb = rowBias ? rowBias + (long)b * strideRB : nullptr;
    #pragma unroll
    for (int ii = 0; ii < 8; ii++) {
        int row = i0 + ((ii < 4) ? (ty * 4 + ii) : (64 + ty * 4 + ii - 4));
        float bias = rb ? rb[row] : 0.f;
        float4 o0, o1;
        o0.x = acc[ii][0] + bias; o0.y = acc[ii][1] + bias;
        o0.z = acc[ii][2] + bias; o0.w = acc[ii][3] + bias;
        o1.x = acc[ii][4] + bias; o1.y = acc[ii][5] + bias;
        o1.z = acc[ii][6] + bias; o1.w = acc[ii][7] + bias;
        *(float4*)(Cm + (long)row * ldc + j0 + tx * 4)      = o0;
        *(float4*)(Cm + (long)row * ldc + j0 + 64 + tx * 4) = o1;
    }
}

// ---------------- tiled SGEMM, NT: C = A(MxK) * B(NxK)^T, row-major ----------------
// Optional rank-1 epilogue: C[i][j] += u1[i]*v1[j] + u2[i]*v2[j]
__global__ __launch_bounds__(256, 2)
void gemm_nt_kernel(const float* __restrict__ A, long strideA,
                    const float* __restrict__ Bm, long strideB,
                    float* __restrict__ Cm, long strideC,
                    int K, int lda, int ldb, int ldc,
                    const float* __restrict__ u1, long su1,
                    const float* __restrict__ v1, long sv1,
                    const float* __restrict__ u2, long su2,
                    const float* __restrict__ v2, long sv2) {
    __shared__ float As[BKK][BM + 4];
    __shared__ float Bs[BKK][BN + 4];
    int b = blockIdx.z;
    A += (long)b * strideA;
    Bm += (long)b * strideB;
    Cm += (long)b * strideC;
    int i0 = blockIdx.y * BM;
    int j0 = blockIdx.x * BN;
    int t = threadIdx.x;
    int tx = t & 15, ty = t >> 4;
    float acc[8][8] = {};
    for (int k0 = 0; k0 < K; k0 += BKK) {
        #pragma unroll
        for (int u = 0; u < 2; u++) {
            int idx = t + u * 256;
            int ar = idx >> 2, akc = (idx & 3) * 4;
            float4 av = *(const float4*)(A + (long)(i0 + ar) * lda + k0 + akc);
            As[akc + 0][ar] = av.x; As[akc + 1][ar] = av.y;
            As[akc + 2][ar] = av.z; As[akc + 3][ar] = av.w;
            float4 bw = *(const float4*)(Bm + (long)(j0 + ar) * ldb + k0 + akc);
            Bs[akc + 0][ar] = bw.x; Bs[akc + 1][ar] = bw.y;
            Bs[akc + 2][ar] = bw.z; Bs[akc + 3][ar] = bw.w;
        }
        __syncthreads();
        #pragma unroll
        for (int kk = 0; kk < BKK; kk++) {
            float a[8], bb[8];
            *(float4*)(a)      = *(const float4*)(&As[kk][ty * 4]);
            *(float4*)(a + 4)  = *(const float4*)(&As[kk][64 + ty * 4]);
            *(float4*)(bb)     = *(const float4*)(&Bs[kk][tx * 4]);
            *(float4*)(bb + 4) = *(const float4*)(&Bs[kk][64 + tx * 4]);
            #pragma unroll
            for (int i = 0; i < 8; i++)
                #pragma unroll
                for (int j = 0; j < 8; j++)
                    acc[i][j] = fmaf(a[i], bb[j], acc[i][j]);
        }
        __syncthreads();
    }
    bool hasR1 = (u1 != nullptr);
    float u1r[8], u2r[8], v1c[8], v2c[8];
    if (hasR1) {
        const float* pu1 = u1 + (long)b * su1;
        const float* pv1 = v1 + (long)b * sv1;
        const float* pu2 = u2 + (long)b * su2;
        const float* pv2 = v2 + (long)b * sv2;
        #pragma unroll
        for (int ii = 0; ii < 8; ii++) {
            int row = i0 + ((ii < 4) ? (ty * 4 + ii) : (64 + ty * 4 + ii - 4));
            u1r[ii] = pu1[row]; u2r[ii] = pu2[row];
        }
        #pragma unroll
        for (int jj = 0; jj < 8; jj++) {
            int col = j0 + ((jj < 4) ? (tx * 4 + jj) : (64 + tx * 4 + jj - 4));
            v1c[jj] = pv1[col]; v2c[jj] = pv2[col];
        }
    }
    #pragma unroll
    for (int ii = 0; ii < 8; ii++) {
        int row = i0 + ((ii < 4) ? (ty * 4 + ii) : (64 + ty * 4 + ii - 4));
        float vals[8];
        #pragma unroll
        for (int jj = 0; jj < 8; jj++) {
            float v = acc[ii][jj];
            if (hasR1) v += u1r[ii] * v1c[jj] + u2r[ii] * v2c[jj];
            vals[jj] = v;
        }
        *(float4*)(Cm + (long)row * ldc + j0 + tx * 4)      = *(float4*)(vals);
        *(float4*)(Cm + (long)row * ldc + j0 + 64 + tx * 4) = *(float4*)(vals + 4);
    }
}

// ---------------- softmax rows of S (in place) + Abv = A*bv ----------------
__global__ void softmax_abv_kernel(float* __restrict__ S, const float* __restrict__ bv,
                                   float* __restrict__ Abv) {
    __shared__ float red[8];
    int row = blockIdx.x;                       // b*CH + i (4096 rows)
    float* p = S + (long)row * CH;
    int t = threadIdx.x;                        // 256 threads, 2 elems each
    float v0 = p[t], v1 = p[t + 256];
    float m = blockReduceMax(fmaxf(v0, v1), red, t, 8);
    float e0 = __expf(v0 - m), e1 = __expf(v1 - m);
    float tot = blockReduceSum(e0 + e1, red, t, 8);
    float inv = 1.0f / tot;
    float a0 = e0 * inv, a1 = e1 * inv;
    p[t] = a0; p[t + 256] = a1;
    float d = blockReduceSum(a0 * bv[t] + a1 * bv[t + 256], red, t, 8);
    if (t == 0) Abv[row] = d;
}

// ---------------- launch ----------------
extern "C" void kernel_launch(void* const* d_in, const int* in_sizes, int n_in,
                              void* d_out, int out_size) {
    const float* x  = (const float*)d_in[0];
    const float* wq = (const float*)d_in[1];
    const float* bq = (const float*)d_in[2];
    const float* wk = (const float*)d_in[3];
    const float* bk = (const float*)d_in[4];
    const float* wv = (const float*)d_in[5];
    const float* bv = (const float*)d_in[6];
    float* out = (float*)d_out;

    float *G, *S, *T, *s, *qs, *ks2, *Abv;
    cudaGetSymbolAddress((void**)&G,   g_G);
    cudaGetSymbolAddress((void**)&S,   g_S);
    cudaGetSymbolAddress((void**)&T,   g_T);
    cudaGetSymbolAddress((void**)&s,   g_s);
    cudaGetSymbolAddress((void**)&qs,  g_qs);
    cudaGetSymbolAddress((void**)&ks2, g_ks2);
    cudaGetSymbolAddress((void**)&Abv, g_Abv);

    const long CN = (long)CH * NPIX;   // per-batch x stride
    const long CC = (long)CH * CH;

    // 1) row sums of X
    rowsum_kernel<<<BATCH * CH, 256>>>(x, s);

    // 2) G[b] = X[b] * X[b]^T   (NT, K=4096)
    gemm_nt_kernel<<<dim3(CH / BN, CH / BM, BATCH), 256>>>(
        x, CN, x, CN, G, CC, NPIX, NPIX, NPIX, CH,
        nullptr, 0, nullptr, 0, nullptr, 0, nullptr, 0);

    // 3) qs = Wq s ; ks2 = Wk s + N*bk
    matvec2_kernel<<<BATCH * CH, 128>>>(wq, wk, bk, s, qs, ks2);

    // 4) T[b] = Wq * G[b]   (NN, K=512)
    gemm_nn_kernel<<<dim3(CH / BN, CH / BM, BATCH), 256>>>(
        wq, 0, G, CC, T, CC, CH, CH, CH, CH, nullptr, 0);

    // 5) S[b] = T[b] * Wk^T + qs[i]*bk[j] + bq[i]*ks2[j]   (NT, K=512)
    gemm_nt_kernel<<<dim3(CH / BN, CH / BM, BATCH), 256>>>(
        T, CC, wk, 0, S, CC, CH, CH, CH, CH,
        qs, CH, bk, 0, bq, 0, ks2, CH);

    // 6) softmax rows -> A (in place), Abv = A*bv
    softmax_abv_kernel<<<BATCH * CH, 256>>>(S, bv, Abv);

    // 7) M[b] = A[b] * Wv   (NN, K=512) -> reuse T
    gemm_nn_kernel<<<dim3(CH / BN, CH / BM, BATCH), 256>>>(
        S, CC, wv, 0, T, CC, CH, CH, CH, CH, nullptr, 0);

    // 8) out[b] = M[b] * X[b] + Abv[i]   (NN, K=512, N=4096)
    gemm_nn_kernel<<<dim3(NPIX / BN, CH / BM, BATCH), 256>>>(
        T, CC, x, CN, out, CN, CH, CH, NPIX, NPIX, Abv, CH);
}